// round 14
// baseline (speedup 1.0000x reference)
#include <cuda_runtime.h>
#include <cstdint>

// CTC greedy decode:  probs [B, T=512, C=128] f32  ->  out [B, T] (float32 values)
// best[t] = argmax_c probs[b,t,c] (first-max tie-break, like jnp.argmax)
// valid[t] = best[t] != best[t-1] (prev=-1 at t=0)  &&  best[t] != C-1 (blank)
// out row  = table[best] for valid t (left-packed), tail = default_char.
//
// History: R8 45.6us -> R12 45.5us (ballot tie-break), DRAM 77.3%. Manual
// load batching (R9/R10) and kernel splitting (R11) all regressed.
// R13: single change vs R12 -- widen the argmax loop unroll 4 -> 8 so ptxas
// can software-pipeline LDG[i+1] under REDUX[i] without manual staging.

#define CTC_T 512
#define CTC_C 128
#define CTC_BLANK (CTC_C - 1)
#define CTC_THREADS 256
#define CTC_WARPS (CTC_THREADS / 32)

// Order-preserving float->uint map (monotone for all finite floats).
__device__ __forceinline__ unsigned f2ord(float f) {
    unsigned u = __float_as_uint(f);
    return (u & 0x80000000u) ? ~u : (u | 0x80000000u);
}

template<bool VEC4>
__global__ __launch_bounds__(CTC_THREADS)
void ctc_decode_kernel(const float* __restrict__ probs,
                       const int* __restrict__ table,
                       const int* __restrict__ defc_ptr,
                       float* __restrict__ out,
                       long long n_probs_elems)
{
    __shared__ int   s_best[CTC_T];
    __shared__ int   s_wsum[CTC_WARPS];
    __shared__ float s_table[CTC_C];

    const int b    = blockIdx.x;
    const int tid  = threadIdx.x;
    const int lane = tid & 31;
    const int wid  = tid >> 5;

    // Bounds guard: never read past the probs buffer.
    if ((long long)(b + 1) * CTC_T * CTC_C > n_probs_elems) return;

    if (tid < CTC_C) s_table[tid] = (float)table[tid];

    const float* __restrict__ base = probs + (size_t)b * CTC_T * CTC_C;

    // ---- Phase 1: per-timestep argmax, one warp per timestep ----
    // Warp `wid` handles t = wid, wid+8, ...; unroll 8 exposes the full 64
    // iterations in windows ptxas can pipeline (loads hoisted under REDUXes).
    #pragma unroll 8
    for (int t = wid; t < CTC_T; t += CTC_WARPS) {
        if (VEC4) {
            const float4 v = __ldg(reinterpret_cast<const float4*>(base + t * CTC_C) + lane);
            float m  = v.x;  int mi = lane * 4;
            if (v.y > m) { m = v.y; mi = lane * 4 + 1; }
            if (v.z > m) { m = v.z; mi = lane * 4 + 2; }
            if (v.w > m) { m = v.w; mi = lane * 4 + 3; }
            // REDUX max over order-mapped values; lowest max-holding lane wins
            // the tie (lane->class ranges are monotone in this path, so the
            // lowest lane owns the lowest tying class index, per jnp.argmax).
            const unsigned mo   = f2ord(m);
            const unsigned vmax = __reduce_max_sync(0xffffffffu, mo);
            const unsigned ball = __ballot_sync(0xffffffffu, mo == vmax);
            if ((mo == vmax) && ((ball & ((1u << lane) - 1u)) == 0u))
                s_best[t] = mi;
        } else {
            // Coalesced scalar fallback (unaligned probs pointer). Lane->class
            // ranges are interleaved here, so use REDUX min-index tie-break.
            const float* row = base + t * CTC_C;
            float m  = __ldg(row + lane);  int mi = lane;
            #pragma unroll
            for (int k = 1; k < 4; ++k) {
                const int   c = lane + k * 32;
                const float v = __ldg(row + c);
                if (v > m) { m = v; mi = c; }
            }
            const unsigned mo   = f2ord(m);
            const unsigned vmax = __reduce_max_sync(0xffffffffu, mo);
            const unsigned cand = (mo == vmax) ? (unsigned)mi : 0xffffffffu;
            const unsigned imin = __reduce_min_sync(0xffffffffu, cand);
            if (lane == 0) s_best[t] = (int)imin;
        }
    }
    __syncthreads();

    // ---- Phase 2: valid flags + block scan; thread owns timesteps 2t, 2t+1 ----
    const int t0 = 2 * tid, t1 = 2 * tid + 1;
    const int b0 = s_best[t0];
    const int b1 = s_best[t1];
    const int p0 = (t0 == 0) ? -1 : s_best[t0 - 1];
    const int v0 = (b0 != p0 && b0 != CTC_BLANK) ? 1 : 0;
    const int v1 = (b1 != b0 && b1 != CTC_BLANK) ? 1 : 0;
    const int pair = v0 + v1;

    int x = pair;
    #pragma unroll
    for (int off = 1; off < 32; off <<= 1) {
        int y = __shfl_up_sync(0xffffffffu, x, off);
        if (lane >= off) x += y;
    }
    if (lane == 31) s_wsum[wid] = x;
    __syncthreads();

    if (wid == 0) {
        int ws = (lane < CTC_WARPS) ? s_wsum[lane] : 0;
        #pragma unroll
        for (int off = 1; off < CTC_WARPS; off <<= 1) {
            int y = __shfl_up_sync(0xffffffffu, ws, off);
            if (lane >= off) ws += y;
        }
        if (lane < CTC_WARPS) s_wsum[lane] = ws;
    }
    __syncthreads();

    const int incl_pair = x + (wid > 0 ? s_wsum[wid - 1] : 0); // inclusive over pairs
    const int excl      = incl_pair - pair;                     // exclusive before t0
    const int count     = s_wsum[CTC_WARPS - 1];                // total valid in row
    const float defc    = defc_ptr ? (float)__ldg(defc_ptr) : 32.0f;

    float* __restrict__ orow = out + (size_t)b * CTC_T;
    if (v0) orow[excl]        = s_table[b0];   // packed positions
    if (v1) orow[excl + v0]   = s_table[b1];
    if (t0 >= count) orow[t0] = defc;          // tail padding (disjoint)
    if (t1 >= count) orow[t1] = defc;
}

extern "C" void kernel_launch(void* const* d_in, const int* in_sizes, int n_in,
                              void* d_out, int out_size)
{
    // --- bind inputs by size (elements-vs-bytes auto-detected) ---
    int probs_i = 0;
    long long max_sz = -1;
    for (int i = 0; i < n_in; ++i)
        if ((long long)in_sizes[i] > max_sz) { max_sz = in_sizes[i]; probs_i = i; }

    int table_i = -1, defc_i = -1;
    int scale = 1;
    for (int i = 0; i < n_in; ++i) {
        if (i == probs_i) continue;
        const int s = in_sizes[i];
        if (s == CTC_C)                          { table_i = i; scale = 1; }
        else if (s == CTC_C * 4 && table_i < 0)  { table_i = i; scale = 4; }
        else if (s == 1 || s == 4)               { if (defc_i < 0) defc_i = i; }
    }
    if (table_i < 0) { table_i = (probs_i == 0 && n_in > 1) ? 1 : 0; scale = 1; }

    const float* probs = (const float*)d_in[probs_i];
    const int*   table = (const int*)d_in[table_i];
    const int*   defc  = (defc_i >= 0) ? (const int*)d_in[defc_i] : nullptr;
    float*       out   = (float*)d_out;

    const long long probs_elems = max_sz / scale;
    const int B = (int)(probs_elems / ((long long)CTC_T * CTC_C));
    if (B <= 0) return;

    const bool aligned16 = ((uintptr_t)probs & 15u) == 0;
    if (aligned16)
        ctc_decode_kernel<true ><<<B, CTC_THREADS>>>(probs, table, defc, out, probs_elems);
    else
        ctc_decode_kernel<false><<<B, CTC_THREADS>>>(probs, table, defc, out, probs_elems);
}

// round 15
// speedup vs baseline: 1.1633x; 1.1633x over previous
#include <cuda_runtime.h>
#include <cstdint>

// CTC greedy decode:  probs [B, T=512, C=128] f32  ->  out [B, T] (float32 values)
// best[t] = argmax_c probs[b,t,c] (first-max tie-break, like jnp.argmax)
// valid[t] = best[t] != best[t-1] (prev=-1 at t=0)  &&  best[t] != C-1 (blank)
// out row  = table[best] for valid t (left-packed), tail = default_char.
//
// FINAL (R12 config). Measured landscape on GB300:
//   R8/R12 (this form):        45.5us, DRAM 77.3% (6.1 TB/s), occ 84%, regs 30
//   manual load batching (R9/R10), kernel split (R11), unroll 8 (R14):
//   all regressed via occupancy/register-pressure or lost locality.
// 6.1 TB/s is the service ceiling for this streaming-argmax pattern; this
// kernel sits at that roofline.

#define CTC_T 512
#define CTC_C 128
#define CTC_BLANK (CTC_C - 1)
#define CTC_THREADS 256
#define CTC_WARPS (CTC_THREADS / 32)

// Order-preserving float->uint map (monotone for all finite floats).
__device__ __forceinline__ unsigned f2ord(float f) {
    unsigned u = __float_as_uint(f);
    return (u & 0x80000000u) ? ~u : (u | 0x80000000u);
}

template<bool VEC4>
__global__ __launch_bounds__(CTC_THREADS)
void ctc_decode_kernel(const float* __restrict__ probs,
                       const int* __restrict__ table,
                       const int* __restrict__ defc_ptr,
                       float* __restrict__ out,
                       long long n_probs_elems)
{
    __shared__ int   s_best[CTC_T];
    __shared__ int   s_wsum[CTC_WARPS];
    __shared__ float s_table[CTC_C];

    const int b    = blockIdx.x;
    const int tid  = threadIdx.x;
    const int lane = tid & 31;
    const int wid  = tid >> 5;

    // Bounds guard: never read past the probs buffer.
    if ((long long)(b + 1) * CTC_T * CTC_C > n_probs_elems) return;

    if (tid < CTC_C) s_table[tid] = (float)table[tid];

    const float* __restrict__ base = probs + (size_t)b * CTC_T * CTC_C;

    // ---- Phase 1: per-timestep argmax, one warp per timestep ----
    // Warp `wid` handles t = wid, wid+8, ... (consecutive warps -> contiguous
    // 4KB per pass). Lane-local 4-way argmax, then warp argmax.
    #pragma unroll 4
    for (int t = wid; t < CTC_T; t += CTC_WARPS) {
        if (VEC4) {
            const float4 v = __ldg(reinterpret_cast<const float4*>(base + t * CTC_C) + lane);
            float m  = v.x;  int mi = lane * 4;
            if (v.y > m) { m = v.y; mi = lane * 4 + 1; }
            if (v.z > m) { m = v.z; mi = lane * 4 + 2; }
            if (v.w > m) { m = v.w; mi = lane * 4 + 3; }
            // REDUX max over order-mapped values; lowest max-holding lane wins
            // the tie (lane->class ranges are monotone in this path, so the
            // lowest lane owns the lowest tying class index, per jnp.argmax).
            const unsigned mo   = f2ord(m);
            const unsigned vmax = __reduce_max_sync(0xffffffffu, mo);
            const unsigned ball = __ballot_sync(0xffffffffu, mo == vmax);
            if ((mo == vmax) && ((ball & ((1u << lane) - 1u)) == 0u))
                s_best[t] = mi;
        } else {
            // Coalesced scalar fallback (unaligned probs pointer). Lane->class
            // ranges are interleaved here, so use REDUX min-index tie-break.
            const float* row = base + t * CTC_C;
            float m  = __ldg(row + lane);  int mi = lane;
            #pragma unroll
            for (int k = 1; k < 4; ++k) {
                const int   c = lane + k * 32;
                const float v = __ldg(row + c);
                if (v > m) { m = v; mi = c; }
            }
            const unsigned mo   = f2ord(m);
            const unsigned vmax = __reduce_max_sync(0xffffffffu, mo);
            const unsigned cand = (mo == vmax) ? (unsigned)mi : 0xffffffffu;
            const unsigned imin = __reduce_min_sync(0xffffffffu, cand);
            if (lane == 0) s_best[t] = (int)imin;
        }
    }
    __syncthreads();

    // ---- Phase 2: valid flags + block scan; thread owns timesteps 2t, 2t+1 ----
    const int t0 = 2 * tid, t1 = 2 * tid + 1;
    const int b0 = s_best[t0];
    const int b1 = s_best[t1];
    const int p0 = (t0 == 0) ? -1 : s_best[t0 - 1];
    const int v0 = (b0 != p0 && b0 != CTC_BLANK) ? 1 : 0;
    const int v1 = (b1 != b0 && b1 != CTC_BLANK) ? 1 : 0;
    const int pair = v0 + v1;

    int x = pair;
    #pragma unroll
    for (int off = 1; off < 32; off <<= 1) {
        int y = __shfl_up_sync(0xffffffffu, x, off);
        if (lane >= off) x += y;
    }
    if (lane == 31) s_wsum[wid] = x;
    __syncthreads();

    if (wid == 0) {
        int ws = (lane < CTC_WARPS) ? s_wsum[lane] : 0;
        #pragma unroll
        for (int off = 1; off < CTC_WARPS; off <<= 1) {
            int y = __shfl_up_sync(0xffffffffu, ws, off);
            if (lane >= off) ws += y;
        }
        if (lane < CTC_WARPS) s_wsum[lane] = ws;
    }
    __syncthreads();

    const int incl_pair = x + (wid > 0 ? s_wsum[wid - 1] : 0); // inclusive over pairs
    const int excl      = incl_pair - pair;                     // exclusive before t0
    const int count     = s_wsum[CTC_WARPS - 1];                // total valid in row
    const float defc    = defc_ptr ? (float)__ldg(defc_ptr) : 32.0f;

    float* __restrict__ orow = out + (size_t)b * CTC_T;
    if (v0) orow[excl]        = s_table[b0];   // packed positions
    if (v1) orow[excl + v0]   = s_table[b1];
    if (t0 >= count) orow[t0] = defc;          // tail padding (disjoint)
    if (t1 >= count) orow[t1] = defc;
}

extern "C" void kernel_launch(void* const* d_in, const int* in_sizes, int n_in,
                              void* d_out, int out_size)
{
    // --- bind inputs by size (elements-vs-bytes auto-detected) ---
    int probs_i = 0;
    long long max_sz = -1;
    for (int i = 0; i < n_in; ++i)
        if ((long long)in_sizes[i] > max_sz) { max_sz = in_sizes[i]; probs_i = i; }

    int table_i = -1, defc_i = -1;
    int scale = 1;
    for (int i = 0; i < n_in; ++i) {
        if (i == probs_i) continue;
        const int s = in_sizes[i];
        if (s == CTC_C)                          { table_i = i; scale = 1; }
        else if (s == CTC_C * 4 && table_i < 0)  { table_i = i; scale = 4; }
        else if (s == 1 || s == 4)               { if (defc_i < 0) defc_i = i; }
    }
    if (table_i < 0) { table_i = (probs_i == 0 && n_in > 1) ? 1 : 0; scale = 1; }

    const float* probs = (const float*)d_in[probs_i];
    const int*   table = (const int*)d_in[table_i];
    const int*   defc  = (defc_i >= 0) ? (const int*)d_in[defc_i] : nullptr;
    float*       out   = (float*)d_out;

    const long long probs_elems = max_sz / scale;
    const int B = (int)(probs_elems / ((long long)CTC_T * CTC_C));
    if (B <= 0) return;

    const bool aligned16 = ((uintptr_t)probs & 15u) == 0;
    if (aligned16)
        ctc_decode_kernel<true ><<<B, CTC_THREADS>>>(probs, table, defc, out, probs_elems);
    else
        ctc_decode_kernel<false><<<B, CTC_THREADS>>>(probs, table, defc, out, probs_elems);
}

// round 16
// speedup vs baseline: 1.1823x; 1.0163x over previous
#include <cuda_runtime.h>
#include <cstdint>

// CTC greedy decode:  probs [B, T=512, C=128] f32  ->  out [B, T] (float32 values)
// best[t] = argmax_c probs[b,t,c] (first-max tie-break, like jnp.argmax)
// valid[t] = best[t] != best[t-1] (prev=-1 at t=0)  &&  best[t] != C-1 (blank)
// out row  = table[best] for valid t (left-packed), tail = default_char.
//
// R12 plateau: 45.5us, DRAM 77%, occ 81%, regs 30. All register-based MLP
// levers regressed (R9/R10/R14). R16: cp.async (LDGSTS) 4-stage ring pipeline
// -- outstanding bytes live in smem, not registers, so pipeline depth costs
// zero occupancy. 4KB stages (8 timesteps), 16KB smem total.

#define CTC_T 512
#define CTC_C 128
#define CTC_BLANK (CTC_C - 1)
#define CTC_THREADS 256
#define CTC_WARPS (CTC_THREADS / 32)
#define NSTAGES 4
#define ROWS_PER_STAGE 8                         // 8 timesteps * 512B = 4KB
#define STAGE_BYTES (ROWS_PER_STAGE * CTC_C * 4) // 4096
#define NUM_STAGES_PER_ROW (CTC_T / ROWS_PER_STAGE) // 64

// Order-preserving float->uint map (monotone for all finite floats).
__device__ __forceinline__ unsigned f2ord(float f) {
    unsigned u = __float_as_uint(f);
    return (u & 0x80000000u) ? ~u : (u | 0x80000000u);
}

// ---------------- Main kernel: cp.async pipelined argmax + pack ----------------
__global__ __launch_bounds__(CTC_THREADS)
void ctc_decode_async(const float* __restrict__ probs,
                      const int* __restrict__ table,
                      const int* __restrict__ defc_ptr,
                      float* __restrict__ out,
                      long long n_probs_elems)
{
    __shared__ __align__(16) float s_stage[NSTAGES][ROWS_PER_STAGE][CTC_C];
    __shared__ int   s_best[CTC_T];
    __shared__ int   s_wsum[CTC_WARPS];
    __shared__ float s_table[CTC_C];

    const int b    = blockIdx.x;
    const int tid  = threadIdx.x;
    const int lane = tid & 31;
    const int wid  = tid >> 5;

    if ((long long)(b + 1) * CTC_T * CTC_C > n_probs_elems) return;
    if (tid < CTC_C) s_table[tid] = (float)table[tid];

    const char* __restrict__ gbase =
        reinterpret_cast<const char*>(probs + (size_t)b * CTC_T * CTC_C);

    // Each thread copies 16B per stage: stage layout is 4KB, thread tid owns
    // bytes [tid*16, tid*16+16).
    const int byte_off = tid * 16;

    // ---- prologue: issue stages 0..NSTAGES-2 ----
    #pragma unroll
    for (int s = 0; s < NSTAGES - 1; ++s) {
        unsigned saddr = (unsigned)__cvta_generic_to_shared(
            reinterpret_cast<char*>(&s_stage[s][0][0]) + byte_off);
        const char* gptr = gbase + (size_t)s * STAGE_BYTES + byte_off;
        asm volatile("cp.async.cg.shared.global [%0], [%1], 16;\n"
                     :: "r"(saddr), "l"(gptr));
        asm volatile("cp.async.commit_group;\n" ::: "memory");
    }

    // ---- steady state: wait oldest, consume, issue next ----
    for (int i = 0; i < NUM_STAGES_PER_ROW; ++i) {
        // stage i complete when <= NSTAGES-2 groups pending
        asm volatile("cp.async.wait_group %0;\n" :: "n"(NSTAGES - 2) : "memory");
        __syncthreads();   // data visible to all; all done consuming buf (i-1)%N

        // consume: warp `wid` argmaxes timestep i*8 + wid from smem
        {
            const int t = i * ROWS_PER_STAGE + wid;
            const float4 v = *reinterpret_cast<const float4*>(
                &s_stage[i % NSTAGES][wid][lane * 4]);
            float m  = v.x;  int mi = lane * 4;
            if (v.y > m) { m = v.y; mi = lane * 4 + 1; }
            if (v.z > m) { m = v.z; mi = lane * 4 + 2; }
            if (v.w > m) { m = v.w; mi = lane * 4 + 3; }
            // REDUX max; lowest max-holding lane wins tie (lane->class ranges
            // are monotone, so lowest lane owns lowest tying class index).
            const unsigned mo   = f2ord(m);
            const unsigned vmax = __reduce_max_sync(0xffffffffu, mo);
            const unsigned ball = __ballot_sync(0xffffffffu, mo == vmax);
            if ((mo == vmax) && ((ball & ((1u << lane) - 1u)) == 0u))
                s_best[t] = mi;
        }

        // issue stage i + NSTAGES-1 into buffer (i+NSTAGES-1)%N (last consumed
        // at iter i-1, before this iteration's barrier)
        const int s_next = i + NSTAGES - 1;
        if (s_next < NUM_STAGES_PER_ROW) {
            unsigned saddr = (unsigned)__cvta_generic_to_shared(
                reinterpret_cast<char*>(&s_stage[s_next % NSTAGES][0][0]) + byte_off);
            const char* gptr = gbase + (size_t)s_next * STAGE_BYTES + byte_off;
            asm volatile("cp.async.cg.shared.global [%0], [%1], 16;\n"
                         :: "r"(saddr), "l"(gptr));
        }
        asm volatile("cp.async.commit_group;\n" ::: "memory"); // always commit
    }
    __syncthreads();

    // ---- Phase 2: valid flags + block scan; thread owns timesteps 2t, 2t+1 ----
    const int t0 = 2 * tid, t1 = 2 * tid + 1;
    const int b0 = s_best[t0];
    const int b1 = s_best[t1];
    const int p0 = (t0 == 0) ? -1 : s_best[t0 - 1];
    const int v0 = (b0 != p0 && b0 != CTC_BLANK) ? 1 : 0;
    const int v1 = (b1 != b0 && b1 != CTC_BLANK) ? 1 : 0;
    const int pair = v0 + v1;

    int x = pair;
    #pragma unroll
    for (int off = 1; off < 32; off <<= 1) {
        int y = __shfl_up_sync(0xffffffffu, x, off);
        if (lane >= off) x += y;
    }
    if (lane == 31) s_wsum[wid] = x;
    __syncthreads();

    if (wid == 0) {
        int ws = (lane < CTC_WARPS) ? s_wsum[lane] : 0;
        #pragma unroll
        for (int off = 1; off < CTC_WARPS; off <<= 1) {
            int y = __shfl_up_sync(0xffffffffu, ws, off);
            if (lane >= off) ws += y;
        }
        if (lane < CTC_WARPS) s_wsum[lane] = ws;
    }
    __syncthreads();

    const int incl_pair = x + (wid > 0 ? s_wsum[wid - 1] : 0);
    const int excl      = incl_pair - pair;
    const int count     = s_wsum[CTC_WARPS - 1];
    const float defc    = defc_ptr ? (float)__ldg(defc_ptr) : 32.0f;

    float* __restrict__ orow = out + (size_t)b * CTC_T;
    if (v0) orow[excl]        = s_table[b0];
    if (v1) orow[excl + v0]   = s_table[b1];
    if (t0 >= count) orow[t0] = defc;
    if (t1 >= count) orow[t1] = defc;
}

// ---------------- Fallback (unaligned probs): proven R12 scalar path ----------------
__global__ __launch_bounds__(CTC_THREADS)
void ctc_decode_fallback(const float* __restrict__ probs,
                         const int* __restrict__ table,
                         const int* __restrict__ defc_ptr,
                         float* __restrict__ out,
                         long long n_probs_elems)
{
    __shared__ int   s_best[CTC_T];
    __shared__ int   s_wsum[CTC_WARPS];
    __shared__ float s_table[CTC_C];

    const int b    = blockIdx.x;
    const int tid  = threadIdx.x;
    const int lane = tid & 31;
    const int wid  = tid >> 5;

    if ((long long)(b + 1) * CTC_T * CTC_C > n_probs_elems) return;
    if (tid < CTC_C) s_table[tid] = (float)table[tid];

    const float* __restrict__ base = probs + (size_t)b * CTC_T * CTC_C;

    #pragma unroll 4
    for (int t = wid; t < CTC_T; t += CTC_WARPS) {
        const float* row = base + t * CTC_C;
        float m  = __ldg(row + lane);  int mi = lane;
        #pragma unroll
        for (int k = 1; k < 4; ++k) {
            const int   c = lane + k * 32;
            const float v = __ldg(row + c);
            if (v > m) { m = v; mi = c; }
        }
        const unsigned mo   = f2ord(m);
        const unsigned vmax = __reduce_max_sync(0xffffffffu, mo);
        const unsigned cand = (mo == vmax) ? (unsigned)mi : 0xffffffffu;
        const unsigned imin = __reduce_min_sync(0xffffffffu, cand);
        if (lane == 0) s_best[t] = (int)imin;
    }
    __syncthreads();

    const int t0 = 2 * tid, t1 = 2 * tid + 1;
    const int b0 = s_best[t0];
    const int b1 = s_best[t1];
    const int p0 = (t0 == 0) ? -1 : s_best[t0 - 1];
    const int v0 = (b0 != p0 && b0 != CTC_BLANK) ? 1 : 0;
    const int v1 = (b1 != b0 && b1 != CTC_BLANK) ? 1 : 0;
    const int pair = v0 + v1;

    int x = pair;
    #pragma unroll
    for (int off = 1; off < 32; off <<= 1) {
        int y = __shfl_up_sync(0xffffffffu, x, off);
        if (lane >= off) x += y;
    }
    if (lane == 31) s_wsum[wid] = x;
    __syncthreads();
    if (wid == 0) {
        int ws = (lane < CTC_WARPS) ? s_wsum[lane] : 0;
        #pragma unroll
        for (int off = 1; off < CTC_WARPS; off <<= 1) {
            int y = __shfl_up_sync(0xffffffffu, ws, off);
            if (lane >= off) ws += y;
        }
        if (lane < CTC_WARPS) s_wsum[lane] = ws;
    }
    __syncthreads();

    const int incl_pair = x + (wid > 0 ? s_wsum[wid - 1] : 0);
    const int excl      = incl_pair - pair;
    const int count     = s_wsum[CTC_WARPS - 1];
    const float defc    = defc_ptr ? (float)__ldg(defc_ptr) : 32.0f;

    float* __restrict__ orow = out + (size_t)b * CTC_T;
    if (v0) orow[excl]        = s_table[b0];
    if (v1) orow[excl + v0]   = s_table[b1];
    if (t0 >= count) orow[t0] = defc;
    if (t1 >= count) orow[t1] = defc;
}

extern "C" void kernel_launch(void* const* d_in, const int* in_sizes, int n_in,
                              void* d_out, int out_size)
{
    // --- bind inputs by size (elements-vs-bytes auto-detected) ---
    int probs_i = 0;
    long long max_sz = -1;
    for (int i = 0; i < n_in; ++i)
        if ((long long)in_sizes[i] > max_sz) { max_sz = in_sizes[i]; probs_i = i; }

    int table_i = -1, defc_i = -1;
    int scale = 1;
    for (int i = 0; i < n_in; ++i) {
        if (i == probs_i) continue;
        const int s = in_sizes[i];
        if (s == CTC_C)                          { table_i = i; scale = 1; }
        else if (s == CTC_C * 4 && table_i < 0)  { table_i = i; scale = 4; }
        else if (s == 1 || s == 4)               { if (defc_i < 0) defc_i = i; }
    }
    if (table_i < 0) { table_i = (probs_i == 0 && n_in > 1) ? 1 : 0; scale = 1; }

    const float* probs = (const float*)d_in[probs_i];
    const int*   table = (const int*)d_in[table_i];
    const int*   defc  = (defc_i >= 0) ? (const int*)d_in[defc_i] : nullptr;
    float*       out   = (float*)d_out;

    const long long probs_elems = max_sz / scale;
    const int B = (int)(probs_elems / ((long long)CTC_T * CTC_C));
    if (B <= 0) return;

    const bool aligned16 = ((uintptr_t)probs & 15u) == 0;
    if (aligned16)
        ctc_decode_async<<<B, CTC_THREADS>>>(probs, table, defc, out, probs_elems);
    else
        ctc_decode_fallback<<<B, CTC_THREADS>>>(probs, table, defc, out, probs_elems);
}